// round 1
// baseline (speedup 1.0000x reference)
#include <cuda_runtime.h>
#include <cuda_bf16.h>

#define H       128
#define MAXN    200000
#define MAXE    600000
#define NTYPES  16
#define TM      64
#define GEMM_THREADS 512
#define GEMM_SMEM (H*TM*4 + H*256*4)   // Xs_t 32KB + Ws_t 128KB = 160KB

// Scratch (static device arrays — no runtime allocation)
__device__ __align__(256) float g_acc[(size_t)MAXN * H];   // self-half + biases, then scatter target
__device__ __align__(256) float g_y[(size_t)MAXN * H];     // y = x @ W_msg^T
__device__ __align__(256) float g_emb2[NTYPES * H];        // edge_emb @ W_msg^T

// ---------------------------------------------------------------------------
// emb2 = edge_emb @ W_msg^T   (16 x 128, tiny)
// ---------------------------------------------------------------------------
__global__ void emb2_kernel(const float* __restrict__ emb, const float* __restrict__ Wm) {
    int i = blockIdx.x;        // 0..15 (edge type)
    int j = threadIdx.x;       // 0..127 (output col)
    const float4* e4 = (const float4*)(emb + i * H);
    const float4* w4 = (const float4*)(Wm + j * H);
    float s = 0.f;
    #pragma unroll
    for (int k = 0; k < H / 4; k++) {
        float4 a = e4[k], b = w4[k];
        s += a.x * b.x + a.y * b.y + a.z * b.z + a.w * b.w;
    }
    g_emb2[i * H + j] = s;
}

// ---------------------------------------------------------------------------
// Fused GEMM: for each node row n
//   g_acc[n,:] = x[n,:] @ W_self^T + b_self + b_msg
//   g_y  [n,:] = x[n,:] @ W_msg^T
// One block = 64 rows, 512 threads, thread micro-tile 8 rows x 4 cols.
// Both weight matrices live (k-transposed) in smem; x tile k-transposed too.
// ---------------------------------------------------------------------------
__global__ __launch_bounds__(GEMM_THREADS, 1)
void gemm_kernel(const float* __restrict__ x,
                 const float* __restrict__ Wself,
                 const float* __restrict__ Wmsg,
                 const float* __restrict__ bself,
                 const float* __restrict__ bmsg,
                 int N) {
    extern __shared__ float smem[];
    float* Xs = smem;            // [H][TM]   : Xs[k*TM + r]
    float* Ws = smem + H * TM;   // [H][256]  : Ws[k*256 + j]

    const int tid  = threadIdx.x;
    const int row0 = blockIdx.x * TM;

    // Load x tile, transpose to Xs[k][r]. 64 rows x 128 k.
    for (int idx = tid; idx < TM * (H / 4); idx += GEMM_THREADS) {
        int r  = idx / (H / 4);
        int k4 = idx % (H / 4);
        int rr = row0 + r; if (rr > N - 1) rr = N - 1;
        float4 v = ((const float4*)(x + (size_t)rr * H))[k4];
        Xs[(k4 * 4 + 0) * TM + r] = v.x;
        Xs[(k4 * 4 + 1) * TM + r] = v.y;
        Xs[(k4 * 4 + 2) * TM + r] = v.z;
        Xs[(k4 * 4 + 3) * TM + r] = v.w;
    }
    // Load both W matrices, transpose to Ws[k][j]; j<128 -> W_self, else W_msg.
    for (int idx = tid; idx < 256 * (H / 4); idx += GEMM_THREADS) {
        int j  = idx / (H / 4);
        int k4 = idx % (H / 4);
        const float* Wrow = (j < H) ? (Wself + (size_t)j * H) : (Wmsg + (size_t)(j - H) * H);
        float4 v = ((const float4*)Wrow)[k4];
        Ws[(k4 * 4 + 0) * 256 + j] = v.x;
        Ws[(k4 * 4 + 1) * 256 + j] = v.y;
        Ws[(k4 * 4 + 2) * 256 + j] = v.z;
        Ws[(k4 * 4 + 3) * 256 + j] = v.w;
    }
    __syncthreads();

    const int ry = tid >> 6;        // 0..7  -> rows ry*8 .. ry*8+7 (uniform per warp)
    const int cx = tid & 63;        // 0..63 -> cols cx*4 .. cx*4+3
    const int r0 = ry * 8;
    const int c0 = cx * 4;

    float acc[8][4];
    #pragma unroll
    for (int r = 0; r < 8; r++)
        #pragma unroll
        for (int c = 0; c < 4; c++) acc[r][c] = 0.f;

    #pragma unroll 8
    for (int k = 0; k < H; k++) {
        float4 a0 = *(const float4*)&Xs[k * TM + r0];       // broadcast within warp
        float4 a1 = *(const float4*)&Xs[k * TM + r0 + 4];
        float4 b  = *(const float4*)&Ws[k * 256 + c0];      // conflict-free
        float av[8] = {a0.x, a0.y, a0.z, a0.w, a1.x, a1.y, a1.z, a1.w};
        #pragma unroll
        for (int r = 0; r < 8; r++) {
            acc[r][0] += av[r] * b.x;
            acc[r][1] += av[r] * b.y;
            acc[r][2] += av[r] * b.z;
            acc[r][3] += av[r] * b.w;
        }
    }

    // Epilogue. Warps 0..7: cx<32 -> self half (+biases) into g_acc;
    //           warps 8..15: cx>=32 -> msg half into g_y.
    if (c0 < H) {
        float4 bias;
        bias.x = bself[c0 + 0] + bmsg[c0 + 0];
        bias.y = bself[c0 + 1] + bmsg[c0 + 1];
        bias.z = bself[c0 + 2] + bmsg[c0 + 2];
        bias.w = bself[c0 + 3] + bmsg[c0 + 3];
        #pragma unroll
        for (int r = 0; r < 8; r++) {
            int row = row0 + r0 + r;
            if (row < N) {
                float4 o = {acc[r][0] + bias.x, acc[r][1] + bias.y,
                            acc[r][2] + bias.z, acc[r][3] + bias.w};
                *(float4*)&g_acc[(size_t)row * H + c0] = o;
            }
        }
    } else {
        int c = c0 - H;
        #pragma unroll
        for (int r = 0; r < 8; r++) {
            int row = row0 + r0 + r;
            if (row < N) {
                float4 o = {acc[r][0], acc[r][1], acc[r][2], acc[r][3]};
                *(float4*)&g_y[(size_t)row * H + c] = o;
            }
        }
    }
}

// ---------------------------------------------------------------------------
// Scatter: for each edge e: g_acc[dst,:] += g_y[src,:] + g_emb2[type,:]
// One warp per edge (grid-stride), 128-bit vector atomics.
// ---------------------------------------------------------------------------
__global__ __launch_bounds__(256)
void scatter_kernel(const int* __restrict__ ei, const int* __restrict__ et, int E) {
    __shared__ float s_emb[NTYPES * H];   // 8 KB
    for (int i = threadIdx.x; i < NTYPES * H; i += 256) s_emb[i] = g_emb2[i];
    __syncthreads();

    const int lane   = threadIdx.x & 31;
    const int warp   = blockIdx.x * 8 + (threadIdx.x >> 5);
    const int stride = gridDim.x * 8;
    const int off    = lane * 4;

    for (int e = warp; e < E; e += stride) {
        int src = ei[e];
        int dst = ei[E + e];
        int t   = et[e];
        float4 v  = *(const float4*)&g_y[(size_t)src * H + off];
        float4 em = *(const float4*)&s_emb[t * H + off];
        v.x += em.x; v.y += em.y; v.z += em.z; v.w += em.w;
        float* p = &g_acc[(size_t)dst * H + off];
        asm volatile("red.global.add.v4.f32 [%0], {%1,%2,%3,%4};"
                     :: "l"(p), "f"(v.x), "f"(v.y), "f"(v.z), "f"(v.w)
                     : "memory");
    }
}

// ---------------------------------------------------------------------------
// ReLU + LayerNorm: one warp per node row.
// ---------------------------------------------------------------------------
__global__ __launch_bounds__(256)
void ln_kernel(const float* __restrict__ gamma, const float* __restrict__ beta,
               float* __restrict__ out, int N) {
    const int lane = threadIdx.x & 31;
    const int row  = blockIdx.x * 8 + (threadIdx.x >> 5);
    if (row >= N) return;

    float4 v = *(const float4*)&g_acc[(size_t)row * H + lane * 4];
    v.x = fmaxf(v.x, 0.f); v.y = fmaxf(v.y, 0.f);
    v.z = fmaxf(v.z, 0.f); v.w = fmaxf(v.w, 0.f);

    float s  = v.x + v.y + v.z + v.w;
    float sq = v.x * v.x + v.y * v.y + v.z * v.z + v.w * v.w;
    #pragma unroll
    for (int o = 16; o > 0; o >>= 1) {
        s  += __shfl_xor_sync(0xffffffffu, s,  o);
        sq += __shfl_xor_sync(0xffffffffu, sq, o);
    }
    float mean = s * (1.f / H);
    float var  = sq * (1.f / H) - mean * mean;
    float rstd = rsqrtf(var + 1e-5f);

    float4 g = *(const float4*)&gamma[lane * 4];
    float4 b = *(const float4*)&beta[lane * 4];
    float4 o;
    o.x = (v.x - mean) * rstd * g.x + b.x;
    o.y = (v.y - mean) * rstd * g.y + b.y;
    o.z = (v.z - mean) * rstd * g.z + b.z;
    o.w = (v.w - mean) * rstd * g.w + b.w;
    *(float4*)&out[(size_t)row * H + lane * 4] = o;
}

// ---------------------------------------------------------------------------
extern "C" void kernel_launch(void* const* d_in, const int* in_sizes, int n_in,
                              void* d_out, int out_size) {
    const float* x     = (const float*)d_in[0];
    const int*   ei    = (const int*)  d_in[1];
    const int*   et    = (const int*)  d_in[2];
    const float* emb   = (const float*)d_in[3];
    const float* Wself = (const float*)d_in[4];
    const float* bself = (const float*)d_in[5];
    const float* Wmsg  = (const float*)d_in[6];
    const float* bmsg  = (const float*)d_in[7];
    const float* gamma = (const float*)d_in[8];
    const float* beta  = (const float*)d_in[9];
    float* out = (float*)d_out;

    const int N = in_sizes[0] / H;
    const int E = in_sizes[1] / 2;

    cudaFuncSetAttribute(gemm_kernel, cudaFuncAttributeMaxDynamicSharedMemorySize, GEMM_SMEM);

    emb2_kernel<<<NTYPES, H>>>(emb, Wmsg);
    gemm_kernel<<<(N + TM - 1) / TM, GEMM_THREADS, GEMM_SMEM>>>(x, Wself, Wmsg, bself, bmsg, N);
    scatter_kernel<<<2048, 256>>>(ei, et, E);
    ln_kernel<<<(N + 7) / 8, 256>>>(gamma, beta, out, N);
}

// round 3
// speedup vs baseline: 2.9807x; 2.9807x over previous
#include <cuda_runtime.h>
#include <cuda_fp16.h>
#include <cstdint>

#define H       128
#define MAXN    200000
#define NTYPES  16

#define SXH     136              // halves per smem row (128 + 8 pad)
#define SXB     (SXH * 2)        // 272 bytes per row -> conflict-free ldmatrix

// smem layout (bytes)
#define SM_BIAS 0                          // 128 floats = 512B
#define SM_XHI  512                        // 128 x 136 halves = 34816B
#define SM_XLO  (SM_XHI + 128 * SXB)
#define SM_WHI  (SM_XLO + 128 * SXB)       // 256 x 136 halves = 69632B
#define SM_TOT  (SM_WHI + 256 * SXB)       // 139,776B

// ---------------- scratch (static device arrays) ----------------
__device__ __align__(256) float g_acc[(size_t)MAXN * H];   // self-half (+biases), then scatter target
__device__ __align__(256) float g_y[(size_t)MAXN * H];     // y = x @ W_msg^T
__device__ __align__(256) float g_emb2[NTYPES * H];        // edge_emb @ W_msg^T

__device__ __forceinline__ uint32_t smem_u32(const void* p) {
    uint32_t a;
    asm("{ .reg .u64 t; cvta.to.shared.u64 t, %1; cvt.u32.u64 %0, t; }" : "=r"(a) : "l"(p));
    return a;
}

__device__ __forceinline__ void ldmx4(uint32_t* r, uint32_t addr) {
    asm volatile("ldmatrix.sync.aligned.m8n8.x4.shared.b16 {%0,%1,%2,%3}, [%4];"
                 : "=r"(r[0]), "=r"(r[1]), "=r"(r[2]), "=r"(r[3]) : "r"(addr));
}

__device__ __forceinline__ void mma16816(float* c, const uint32_t* a, uint32_t b0, uint32_t b1) {
    asm volatile("mma.sync.aligned.m16n8k16.row.col.f32.f16.f16.f32 "
                 "{%0,%1,%2,%3}, {%4,%5,%6,%7}, {%8,%9}, {%0,%1,%2,%3};"
                 : "+f"(c[0]), "+f"(c[1]), "+f"(c[2]), "+f"(c[3])
                 : "r"(a[0]), "r"(a[1]), "r"(a[2]), "r"(a[3]), "r"(b0), "r"(b1));
}

__device__ __forceinline__ uint32_t h2u(__half2 h) { return *reinterpret_cast<uint32_t*>(&h); }

// split fp32x4 -> hi fp16x4 (8B) + lo fp16x4 (8B)
__device__ __forceinline__ void split4(char* hi, char* lo, uint32_t off, float4 v) {
    __half2 h0 = __float22half2_rn(make_float2(v.x, v.y));
    __half2 h1 = __float22half2_rn(make_float2(v.z, v.w));
    float2 f0 = __half22float2(h0);
    float2 f1 = __half22float2(h1);
    __half2 l0 = __float22half2_rn(make_float2(v.x - f0.x, v.y - f0.y));
    __half2 l1 = __float22half2_rn(make_float2(v.z - f1.x, v.w - f1.y));
    *reinterpret_cast<uint2*>(hi + off) = make_uint2(h2u(h0), h2u(h1));
    *reinterpret_cast<uint2*>(lo + off) = make_uint2(h2u(l0), h2u(l1));
}

// ---------------------------------------------------------------------------
// emb2 = edge_emb @ W_msg^T   (16 x 128, tiny, fp32)
// ---------------------------------------------------------------------------
__global__ void emb2_kernel(const float* __restrict__ emb, const float* __restrict__ Wm) {
    int i = blockIdx.x, j = threadIdx.x;
    const float4* e4 = (const float4*)(emb + i * H);
    const float4* w4 = (const float4*)(Wm + j * H);
    float s = 0.f;
    #pragma unroll
    for (int k = 0; k < H / 4; k++) {
        float4 a = e4[k], b = w4[k];
        s += a.x * b.x + a.y * b.y + a.z * b.z + a.w * b.w;
    }
    g_emb2[i * H + j] = s;
}

// ---------------------------------------------------------------------------
// Tensor-core GEMM (persistent, mma.sync fp16 2-pass split):
//   D[:,0:128]   = x_tile @ W_self^T  -> g_acc (+ bself + bmsg)
//   D[:,128:256] = x_tile @ W_msg^T   -> g_y
// 512 threads = 16 warps; warp tile 64(m) x 32(n); block tile 128 x 256.
// ---------------------------------------------------------------------------
__global__ __launch_bounds__(512, 1)
void gemm_tc_kernel(const float* __restrict__ x,
                    const float* __restrict__ Wself,
                    const float* __restrict__ Wmsg,
                    const float* __restrict__ bself,
                    const float* __restrict__ bmsg,
                    int N) {
    extern __shared__ char smem[];
    const uint32_t sb = smem_u32(smem);
    float* s_bias = (float*)(smem + SM_BIAS);

    const int tid  = threadIdx.x;
    const int wid  = tid >> 5, lane = tid & 31;
    const int wm   = (wid >> 3) * 64;     // warp row offset in tile
    const int wn   = (wid & 7) * 32;      // warp col offset (0..224)

    if (tid < H) s_bias[tid] = bself[tid] + bmsg[tid];

    // ---- W hi (fp16) into smem, once. thread -> (row n, k-half) ----
    {
        const int n  = tid >> 1;
        const int kh = (tid & 1) * 64;
        const float* wrow = (n < H) ? (Wself + (size_t)n * H) : (Wmsg + (size_t)(n - H) * H);
        const float4* w4 = (const float4*)(wrow + kh);
        char* dst = smem + SM_WHI + n * SXB + kh * 2;
        #pragma unroll 4
        for (int i = 0; i < 16; i++) {
            float4 v = w4[i];
            __half2 h0 = __float22half2_rn(make_float2(v.x, v.y));
            __half2 h1 = __float22half2_rn(make_float2(v.z, v.w));
            *reinterpret_cast<uint2*>(dst + i * 8) = make_uint2(h2u(h0), h2u(h1));
        }
    }
    __syncthreads();

    // ldmatrix base addresses (per lane)
    const uint32_t aHiB = sb + SM_XHI + (wm + (lane & 15)) * SXB + (lane >> 4) * 16;
    const uint32_t aLoB = sb + SM_XLO + (wm + (lane & 15)) * SXB + (lane >> 4) * 16;
    const uint32_t bB   = sb + SM_WHI + (wn + (lane & 15)) * SXB + (lane >> 4) * 16;

    const int ntiles = (N + 127) >> 7;

    // X-fill indexing: thread -> (row, k-quarter of 32)
    const int fr = tid >> 2;
    const int fk = (tid & 3) * 32;

    for (int t = blockIdx.x; t < ntiles; t += gridDim.x) {
        const int row0 = t << 7;

        __syncthreads();   // previous tile's mma readers done before overwrite

        // ---- fill X tile (split hi/lo fp16) ----
        {
            int gr = row0 + fr; if (gr > N - 1) gr = N - 1;
            const float4* xr = (const float4*)(x + (size_t)gr * H + fk);
            const uint32_t base = fr * SXB + fk * 2;
            #pragma unroll 8
            for (int i = 0; i < 8; i++)
                split4(smem + SM_XHI, smem + SM_XLO, base + i * 8, xr[i]);
        }
        __syncthreads();

        float acc[4][4][4];
        #pragma unroll
        for (int mt = 0; mt < 4; mt++)
            #pragma unroll
            for (int nt = 0; nt < 4; nt++)
                #pragma unroll
                for (int j = 0; j < 4; j++) acc[mt][nt][j] = 0.f;

        // ---- K loop: 8 k-steps of 16 ----
        #pragma unroll
        for (int ks = 0; ks < 8; ks++) {
            const uint32_t ko = ks * 32;
            uint32_t bf[2][4];
            ldmx4(bf[0], bB + ko);                 // n-tiles 0,1
            ldmx4(bf[1], bB + 16 * SXB + ko);      // n-tiles 2,3

            #pragma unroll
            for (int mt = 0; mt < 4; mt++) {
                uint32_t a[4];
                ldmx4(a, aHiB + mt * 16 * SXB + ko);
                mma16816(acc[mt][0], a, bf[0][0], bf[0][2]);
                mma16816(acc[mt][1], a, bf[0][1], bf[0][3]);
                mma16816(acc[mt][2], a, bf[1][0], bf[1][2]);
                mma16816(acc[mt][3], a, bf[1][1], bf[1][3]);
                ldmx4(a, aLoB + mt * 16 * SXB + ko);
                mma16816(acc[mt][0], a, bf[0][0], bf[0][2]);
                mma16816(acc[mt][1], a, bf[0][1], bf[0][3]);
                mma16816(acc[mt][2], a, bf[1][0], bf[1][2]);
                mma16816(acc[mt][3], a, bf[1][1], bf[1][3]);
            }
        }

        // ---- epilogue: direct fp32 stores from register accumulators ----
        const int cbase = wn + (lane & 3) * 2;        // global output col (0..255)
        const bool self_half = (cbase < H);
        const int c = self_half ? cbase : cbase - H;
        float2 bias2 = make_float2(0.f, 0.f);
        float* gbase = self_half ? g_acc : g_y;

        #pragma unroll
        for (int nt = 0; nt < 4; nt++) {
            const int cc = c + nt * 8;
            if (self_half) bias2 = *(const float2*)&s_bias[cc];
            #pragma unroll
            for (int mt = 0; mt < 4; mt++) {
                const int r0 = row0 + wm + mt * 16 + (lane >> 2);
                const int r1 = r0 + 8;
                if (r0 < N) {
                    float2 o = make_float2(acc[mt][nt][0] + bias2.x, acc[mt][nt][1] + bias2.y);
                    *(float2*)&gbase[(size_t)r0 * H + cc] = o;
                }
                if (r1 < N) {
                    float2 o = make_float2(acc[mt][nt][2] + bias2.x, acc[mt][nt][3] + bias2.y);
                    *(float2*)&gbase[(size_t)r1 * H + cc] = o;
                }
            }
        }
    }
}

// ---------------------------------------------------------------------------
// Scatter: g_acc[dst,:] += g_y[src,:] + g_emb2[type,:]  (one warp per edge)
// ---------------------------------------------------------------------------
__global__ __launch_bounds__(256)
void scatter_kernel(const int* __restrict__ ei, const int* __restrict__ et, int E) {
    __shared__ float s_emb[NTYPES * H];
    for (int i = threadIdx.x; i < NTYPES * H; i += 256) s_emb[i] = g_emb2[i];
    __syncthreads();

    const int lane   = threadIdx.x & 31;
    const int warp   = blockIdx.x * 8 + (threadIdx.x >> 5);
    const int stride = gridDim.x * 8;
    const int off    = lane * 4;

    for (int e = warp; e < E; e += stride) {
        int src = ei[e];
        int dst = ei[E + e];
        int ty  = et[e];
        float4 v  = *(const float4*)&g_y[(size_t)src * H + off];
        float4 em = *(const float4*)&s_emb[ty * H + off];
        v.x += em.x; v.y += em.y; v.z += em.z; v.w += em.w;
        float* p = &g_acc[(size_t)dst * H + off];
        asm volatile("red.global.add.v4.f32 [%0], {%1,%2,%3,%4};"
                     :: "l"(p), "f"(v.x), "f"(v.y), "f"(v.z), "f"(v.w) : "memory");
    }
}

// ---------------------------------------------------------------------------
// ReLU + LayerNorm (one warp per node row)
// ---------------------------------------------------------------------------
__global__ __launch_bounds__(256)
void ln_kernel(const float* __restrict__ gamma, const float* __restrict__ beta,
               float* __restrict__ out, int N) {
    const int lane = threadIdx.x & 31;
    const int row  = blockIdx.x * 8 + (threadIdx.x >> 5);
    if (row >= N) return;

    float4 v = *(const float4*)&g_acc[(size_t)row * H + lane * 4];
    v.x = fmaxf(v.x, 0.f); v.y = fmaxf(v.y, 0.f);
    v.z = fmaxf(v.z, 0.f); v.w = fmaxf(v.w, 0.f);

    float s  = v.x + v.y + v.z + v.w;
    float sq = v.x * v.x + v.y * v.y + v.z * v.z + v.w * v.w;
    #pragma unroll
    for (int o = 16; o > 0; o >>= 1) {
        s  += __shfl_xor_sync(0xffffffffu, s,  o);
        sq += __shfl_xor_sync(0xffffffffu, sq, o);
    }
    float mean = s * (1.f / H);
    float var  = sq * (1.f / H) - mean * mean;
    float rstd = rsqrtf(var + 1e-5f);

    float4 g = *(const float4*)&gamma[lane * 4];
    float4 b = *(const float4*)&beta[lane * 4];
    float4 o;
    o.x = (v.x - mean) * rstd * g.x + b.x;
    o.y = (v.y - mean) * rstd * g.y + b.y;
    o.z = (v.z - mean) * rstd * g.z + b.z;
    o.w = (v.w - mean) * rstd * g.w + b.w;
    *(float4*)&out[(size_t)row * H + lane * 4] = o;
}

// ---------------------------------------------------------------------------
extern "C" void kernel_launch(void* const* d_in, const int* in_sizes, int n_in,
                              void* d_out, int out_size) {
    const float* x     = (const float*)d_in[0];
    const int*   ei    = (const int*)  d_in[1];
    const int*   et    = (const int*)  d_in[2];
    const float* emb   = (const float*)d_in[3];
    const float* Wself = (const float*)d_in[4];
    const float* bself = (const float*)d_in[5];
    const float* Wmsg  = (const float*)d_in[6];
    const float* bmsg  = (const float*)d_in[7];
    const float* gamma = (const float*)d_in[8];
    const float* beta  = (const float*)d_in[9];
    float* out = (float*)d_out;

    const int N = in_sizes[0] / H;
    const int E = in_sizes[1] / 2;

    cudaFuncSetAttribute(gemm_tc_kernel, cudaFuncAttributeMaxDynamicSharedMemorySize, SM_TOT);

    emb2_kernel<<<NTYPES, H>>>(emb, Wmsg);
    gemm_tc_kernel<<<152, 512, SM_TOT>>>(x, Wself, Wmsg, bself, bmsg, N);
    scatter_kernel<<<2048, 256>>>(ei, et, E);
    ln_kernel<<<(N + 7) / 8, 256>>>(gamma, beta, out, N);
}

// round 4
// speedup vs baseline: 3.0625x; 1.0274x over previous
#include <cuda_runtime.h>
#include <cuda_fp16.h>
#include <cstdint>

#define H       128
#define MAXN    200000
#define MAXE    600000
#define NTYPES  16

#define SXH     136              // halves per smem row (128 + 8 pad)
#define SXB     (SXH * 2)        // 272 bytes per row -> conflict-free ldmatrix

// smem layout (bytes) for GEMM
#define SM_BIAS 0                          // 128 floats = 512B
#define SM_XHI  512                        // 128 x 136 halves = 34816B
#define SM_XLO  (SM_XHI + 128 * SXB)
#define SM_WHI  (SM_XLO + 128 * SXB)       // 256 x 136 halves = 69632B
#define SM_TOT  (SM_WHI + 256 * SXB)       // 139,776B

// ---------------- scratch (static device arrays) ----------------
__device__ __align__(256) float g_acc[(size_t)MAXN * H];   // self-half (+biases)
__device__ __align__(256) float g_y[(size_t)MAXN * H];     // y = x @ W_msg^T
__device__ __align__(256) float g_emb2[NTYPES * H];        // edge_emb @ W_msg^T
__device__ int g_deg[MAXN];
__device__ int g_start[MAXN];
__device__ int g_cursor[MAXN];
__device__ int g_pk[MAXE];                                 // packed src | type<<24
__device__ int g_total;

__device__ __forceinline__ uint32_t smem_u32(const void* p) {
    uint32_t a;
    asm("{ .reg .u64 t; cvta.to.shared.u64 t, %1; cvt.u32.u64 %0, t; }" : "=r"(a) : "l"(p));
    return a;
}

__device__ __forceinline__ void ldmx4(uint32_t* r, uint32_t addr) {
    asm volatile("ldmatrix.sync.aligned.m8n8.x4.shared.b16 {%0,%1,%2,%3}, [%4];"
                 : "=r"(r[0]), "=r"(r[1]), "=r"(r[2]), "=r"(r[3]) : "r"(addr));
}

__device__ __forceinline__ void mma16816(float* c, const uint32_t* a, uint32_t b0, uint32_t b1) {
    asm volatile("mma.sync.aligned.m16n8k16.row.col.f32.f16.f16.f32 "
                 "{%0,%1,%2,%3}, {%4,%5,%6,%7}, {%8,%9}, {%0,%1,%2,%3};"
                 : "+f"(c[0]), "+f"(c[1]), "+f"(c[2]), "+f"(c[3])
                 : "r"(a[0]), "r"(a[1]), "r"(a[2]), "r"(a[3]), "r"(b0), "r"(b1));
}

__device__ __forceinline__ uint32_t h2u(__half2 h) { return *reinterpret_cast<uint32_t*>(&h); }

// split fp32x4 -> hi fp16x4 (8B) + lo fp16x4 (8B)
__device__ __forceinline__ void split4(char* hi, char* lo, uint32_t off, float4 v) {
    __half2 h0 = __float22half2_rn(make_float2(v.x, v.y));
    __half2 h1 = __float22half2_rn(make_float2(v.z, v.w));
    float2 f0 = __half22float2(h0);
    float2 f1 = __half22float2(h1);
    __half2 l0 = __float22half2_rn(make_float2(v.x - f0.x, v.y - f0.y));
    __half2 l1 = __float22half2_rn(make_float2(v.z - f1.x, v.w - f1.y));
    *reinterpret_cast<uint2*>(hi + off) = make_uint2(h2u(h0), h2u(h1));
    *reinterpret_cast<uint2*>(lo + off) = make_uint2(h2u(l0), h2u(l1));
}

// ---------------------------------------------------------------------------
// emb2 = edge_emb @ W_msg^T
// ---------------------------------------------------------------------------
__global__ void emb2_kernel(const float* __restrict__ emb, const float* __restrict__ Wm) {
    int i = blockIdx.x, j = threadIdx.x;
    const float4* e4 = (const float4*)(emb + i * H);
    const float4* w4 = (const float4*)(Wm + j * H);
    float s = 0.f;
    #pragma unroll
    for (int k = 0; k < H / 4; k++) {
        float4 a = e4[k], b = w4[k];
        s += a.x * b.x + a.y * b.y + a.z * b.z + a.w * b.w;
    }
    g_emb2[i * H + j] = s;
}

// ---------------------------------------------------------------------------
// Tensor-core GEMM (persistent, mma.sync fp16 2-pass split) — same as round 3
// ---------------------------------------------------------------------------
__global__ __launch_bounds__(512, 1)
void gemm_tc_kernel(const float* __restrict__ x,
                    const float* __restrict__ Wself,
                    const float* __restrict__ Wmsg,
                    const float* __restrict__ bself,
                    const float* __restrict__ bmsg,
                    int N) {
    extern __shared__ char smem[];
    const uint32_t sb = smem_u32(smem);
    float* s_bias = (float*)(smem + SM_BIAS);

    const int tid  = threadIdx.x;
    const int wid  = tid >> 5, lane = tid & 31;
    const int wm   = (wid >> 3) * 64;
    const int wn   = (wid & 7) * 32;

    if (tid < H) s_bias[tid] = bself[tid] + bmsg[tid];

    {
        const int n  = tid >> 1;
        const int kh = (tid & 1) * 64;
        const float* wrow = (n < H) ? (Wself + (size_t)n * H) : (Wmsg + (size_t)(n - H) * H);
        const float4* w4 = (const float4*)(wrow + kh);
        char* dst = smem + SM_WHI + n * SXB + kh * 2;
        #pragma unroll 4
        for (int i = 0; i < 16; i++) {
            float4 v = w4[i];
            __half2 h0 = __float22half2_rn(make_float2(v.x, v.y));
            __half2 h1 = __float22half2_rn(make_float2(v.z, v.w));
            *reinterpret_cast<uint2*>(dst + i * 8) = make_uint2(h2u(h0), h2u(h1));
        }
    }
    __syncthreads();

    const uint32_t aHiB = sb + SM_XHI + (wm + (lane & 15)) * SXB + (lane >> 4) * 16;
    const uint32_t aLoB = sb + SM_XLO + (wm + (lane & 15)) * SXB + (lane >> 4) * 16;
    const uint32_t bB   = sb + SM_WHI + (wn + (lane & 15)) * SXB + (lane >> 4) * 16;

    const int ntiles = (N + 127) >> 7;
    const int fr = tid >> 2;
    const int fk = (tid & 3) * 32;

    for (int t = blockIdx.x; t < ntiles; t += gridDim.x) {
        const int row0 = t << 7;

        __syncthreads();

        {
            int gr = row0 + fr; if (gr > N - 1) gr = N - 1;
            const float4* xr = (const float4*)(x + (size_t)gr * H + fk);
            const uint32_t base = fr * SXB + fk * 2;
            #pragma unroll 8
            for (int i = 0; i < 8; i++)
                split4(smem + SM_XHI, smem + SM_XLO, base + i * 8, xr[i]);
        }
        __syncthreads();

        float acc[4][4][4];
        #pragma unroll
        for (int mt = 0; mt < 4; mt++)
            #pragma unroll
            for (int nt = 0; nt < 4; nt++)
                #pragma unroll
                for (int j = 0; j < 4; j++) acc[mt][nt][j] = 0.f;

        #pragma unroll
        for (int ks = 0; ks < 8; ks++) {
            const uint32_t ko = ks * 32;
            uint32_t bf[2][4];
            ldmx4(bf[0], bB + ko);
            ldmx4(bf[1], bB + 16 * SXB + ko);

            #pragma unroll
            for (int mt = 0; mt < 4; mt++) {
                uint32_t a[4];
                ldmx4(a, aHiB + mt * 16 * SXB + ko);
                mma16816(acc[mt][0], a, bf[0][0], bf[0][2]);
                mma16816(acc[mt][1], a, bf[0][1], bf[0][3]);
                mma16816(acc[mt][2], a, bf[1][0], bf[1][2]);
                mma16816(acc[mt][3], a, bf[1][1], bf[1][3]);
                ldmx4(a, aLoB + mt * 16 * SXB + ko);
                mma16816(acc[mt][0], a, bf[0][0], bf[0][2]);
                mma16816(acc[mt][1], a, bf[0][1], bf[0][3]);
                mma16816(acc[mt][2], a, bf[1][0], bf[1][2]);
                mma16816(acc[mt][3], a, bf[1][1], bf[1][3]);
            }
        }

        const int cbase = wn + (lane & 3) * 2;
        const bool self_half = (cbase < H);
        const int c = self_half ? cbase : cbase - H;
        float2 bias2 = make_float2(0.f, 0.f);
        float* gbase = self_half ? g_acc : g_y;

        #pragma unroll
        for (int nt = 0; nt < 4; nt++) {
            const int cc = c + nt * 8;
            if (self_half) bias2 = *(const float2*)&s_bias[cc];
            #pragma unroll
            for (int mt = 0; mt < 4; mt++) {
                const int r0 = row0 + wm + mt * 16 + (lane >> 2);
                const int r1 = r0 + 8;
                if (r0 < N) {
                    float2 o = make_float2(acc[mt][nt][0] + bias2.x, acc[mt][nt][1] + bias2.y);
                    *(float2*)&gbase[(size_t)r0 * H + cc] = o;
                }
                if (r1 < N) {
                    float2 o = make_float2(acc[mt][nt][2] + bias2.x, acc[mt][nt][3] + bias2.y);
                    *(float2*)&gbase[(size_t)r1 * H + cc] = o;
                }
            }
        }
    }
}

// ---------------------------------------------------------------------------
// CSR build: zero -> hist -> assign(starts via warp-scan) -> fill(slots)
// ---------------------------------------------------------------------------
__global__ __launch_bounds__(1024)
void zero_kernel(int N) {
    int i = blockIdx.x * 1024 + threadIdx.x;
    if (i < N) g_deg[i] = 0;
    if (i == 0) g_total = 0;
}

__global__ __launch_bounds__(512)
void hist_kernel(const int* __restrict__ ei, int E) {
    int i = blockIdx.x * 512 + threadIdx.x;
    int stride = gridDim.x * 512;
    for (int e = i; e < E; e += stride)
        atomicAdd(&g_deg[ei[E + e]], 1);
}

__global__ __launch_bounds__(256)
void assign_kernel(int N) {
    const int n    = blockIdx.x * 256 + threadIdx.x;
    const int lane = threadIdx.x & 31;
    int d = (n < N) ? g_deg[n] : 0;
    // inclusive warp scan
    int s = d;
    #pragma unroll
    for (int o = 1; o < 32; o <<= 1) {
        int t = __shfl_up_sync(0xffffffffu, s, o);
        if (lane >= o) s += t;
    }
    int base = 0;
    if (lane == 31) base = atomicAdd(&g_total, s);
    base = __shfl_sync(0xffffffffu, base, 31);
    if (n < N) {
        int st = base + s - d;
        g_start[n]  = st;
        g_cursor[n] = st;
    }
}

__global__ __launch_bounds__(512)
void fill_kernel(const int* __restrict__ ei, const int* __restrict__ et, int E) {
    int i = blockIdx.x * 512 + threadIdx.x;
    int stride = gridDim.x * 512;
    for (int e = i; e < E; e += stride) {
        int src = ei[e];
        int dst = ei[E + e];
        int ty  = et[e];
        int slot = atomicAdd(&g_cursor[dst], 1);
        g_pk[slot] = src | (ty << 24);
    }
}

// ---------------------------------------------------------------------------
// Fused aggregate + ReLU + LayerNorm: one warp per node row.
//   v = g_acc[row] + sum_{e in CSR[row]} (g_y[src_e] + emb2[type_e])
//   out[row] = LN(relu(v)) * gamma + beta
// ---------------------------------------------------------------------------
__global__ __launch_bounds__(256)
void aggregate_ln_kernel(const float* __restrict__ gamma, const float* __restrict__ beta,
                         float* __restrict__ out, int N) {
    __shared__ float s_emb[NTYPES * H];
    for (int i = threadIdx.x; i < NTYPES * H; i += 256) s_emb[i] = g_emb2[i];
    __syncthreads();

    const int lane = threadIdx.x & 31;
    const int row  = blockIdx.x * 8 + (threadIdx.x >> 5);
    if (row >= N) return;
    const int off = lane * 4;

    float4 v = *(const float4*)&g_acc[(size_t)row * H + off];

    const int st = g_start[row];
    const int en = st + g_deg[row];
    for (int i = st; i < en; i++) {
        int p   = g_pk[i];
        int src = p & 0xFFFFFF;
        int ty  = p >> 24;
        float4 m  = *(const float4*)&g_y[(size_t)src * H + off];
        float4 em = *(const float4*)&s_emb[ty * H + off];
        v.x += m.x + em.x; v.y += m.y + em.y;
        v.z += m.z + em.z; v.w += m.w + em.w;
    }

    v.x = fmaxf(v.x, 0.f); v.y = fmaxf(v.y, 0.f);
    v.z = fmaxf(v.z, 0.f); v.w = fmaxf(v.w, 0.f);

    float s  = v.x + v.y + v.z + v.w;
    float sq = v.x * v.x + v.y * v.y + v.z * v.z + v.w * v.w;
    #pragma unroll
    for (int o = 16; o > 0; o >>= 1) {
        s  += __shfl_xor_sync(0xffffffffu, s,  o);
        sq += __shfl_xor_sync(0xffffffffu, sq, o);
    }
    float mean = s * (1.f / H);
    float var  = sq * (1.f / H) - mean * mean;
    float rstd = rsqrtf(var + 1e-5f);

    float4 g = *(const float4*)&gamma[off];
    float4 b = *(const float4*)&beta[off];
    float4 o;
    o.x = (v.x - mean) * rstd * g.x + b.x;
    o.y = (v.y - mean) * rstd * g.y + b.y;
    o.z = (v.z - mean) * rstd * g.z + b.z;
    o.w = (v.w - mean) * rstd * g.w + b.w;
    *(float4*)&out[(size_t)row * H + off] = o;
}

// ---------------------------------------------------------------------------
extern "C" void kernel_launch(void* const* d_in, const int* in_sizes, int n_in,
                              void* d_out, int out_size) {
    const float* x     = (const float*)d_in[0];
    const int*   ei    = (const int*)  d_in[1];
    const int*   et    = (const int*)  d_in[2];
    const float* emb   = (const float*)d_in[3];
    const float* Wself = (const float*)d_in[4];
    const float* bself = (const float*)d_in[5];
    const float* Wmsg  = (const float*)d_in[6];
    const float* bmsg  = (const float*)d_in[7];
    const float* gamma = (const float*)d_in[8];
    const float* beta  = (const float*)d_in[9];
    float* out = (float*)d_out;

    const int N = in_sizes[0] / H;
    const int E = in_sizes[1] / 2;

    cudaFuncSetAttribute(gemm_tc_kernel, cudaFuncAttributeMaxDynamicSharedMemorySize, SM_TOT);

    emb2_kernel<<<NTYPES, H>>>(emb, Wmsg);
    gemm_tc_kernel<<<152, 512, SM_TOT>>>(x, Wself, Wmsg, bself, bmsg, N);

    zero_kernel<<<(N + 1023) / 1024, 1024>>>(N);
    hist_kernel<<<592, 512>>>(ei, E);
    assign_kernel<<<(N + 255) / 256, 256>>>(N);
    fill_kernel<<<592, 512>>>(ei, et, E);
    aggregate_ln_kernel<<<(N + 7) / 8, 256>>>(gamma, beta, out, N);
}

// round 5
// speedup vs baseline: 3.3305x; 1.0875x over previous
#include <cuda_runtime.h>
#include <cuda_fp16.h>
#include <cstdint>

#define H       128
#define MAXN    200000
#define MAXE    600000
#define NTYPES  16

#define SXH     136              // halves per smem row (128 + 8 pad)
#define SXB     (SXH * 2)        // 272 bytes per row -> conflict-free ldmatrix

// smem layout (bytes) for GEMM
#define SM_BIAS 0                          // 128 floats = 512B
#define SM_XHI  512                        // 128 x 136 halves = 34816B
#define SM_XLO  (SM_XHI + 128 * SXB)
#define SM_WHI  (SM_XLO + 128 * SXB)       // 256 x 136 halves = 69632B
#define SM_TOT  (SM_WHI + 256 * SXB)       // 139,776B

// ---------------- scratch (static device arrays) ----------------
__device__ __align__(256) float  g_acc[(size_t)MAXN * H];   // self-half (+biases)
__device__ __align__(256) __half g_y[(size_t)MAXN * H];     // y = x @ W_msg^T (fp16)
__device__ __align__(256) float  g_emb2[NTYPES * H];        // edge_emb @ W_msg^T
__device__ int g_deg[MAXN];
__device__ int g_start[MAXN];
__device__ int g_cursor[MAXN];
__device__ int g_pk[MAXE];                                  // packed src | type<<24
__device__ int g_total;

__device__ __forceinline__ uint32_t smem_u32(const void* p) {
    uint32_t a;
    asm("{ .reg .u64 t; cvta.to.shared.u64 t, %1; cvt.u32.u64 %0, t; }" : "=r"(a) : "l"(p));
    return a;
}

__device__ __forceinline__ void ldmx4(uint32_t* r, uint32_t addr) {
    asm volatile("ldmatrix.sync.aligned.m8n8.x4.shared.b16 {%0,%1,%2,%3}, [%4];"
                 : "=r"(r[0]), "=r"(r[1]), "=r"(r[2]), "=r"(r[3]) : "r"(addr));
}

// f32-accumulate mma (hi pass)
__device__ __forceinline__ void mma_f32(float* c, const uint32_t* a, uint32_t b0, uint32_t b1) {
    asm volatile("mma.sync.aligned.m16n8k16.row.col.f32.f16.f16.f32 "
                 "{%0,%1,%2,%3}, {%4,%5,%6,%7}, {%8,%9}, {%0,%1,%2,%3};"
                 : "+f"(c[0]), "+f"(c[1]), "+f"(c[2]), "+f"(c[3])
                 : "r"(a[0]), "r"(a[1]), "r"(a[2]), "r"(a[3]), "r"(b0), "r"(b1));
}

// f16-accumulate mma (lo pass; 2x issue rate)
__device__ __forceinline__ void mma_f16(uint32_t* c, const uint32_t* a, uint32_t b0, uint32_t b1) {
    asm volatile("mma.sync.aligned.m16n8k16.row.col.f16.f16.f16.f16 "
                 "{%0,%1}, {%2,%3,%4,%5}, {%6,%7}, {%0,%1};"
                 : "+r"(c[0]), "+r"(c[1])
                 : "r"(a[0]), "r"(a[1]), "r"(a[2]), "r"(a[3]), "r"(b0), "r"(b1));
}

__device__ __forceinline__ uint32_t h2u(__half2 h) { return *reinterpret_cast<uint32_t*>(&h); }
__device__ __forceinline__ __half2 u2h(uint32_t u) { return *reinterpret_cast<__half2*>(&u); }

// split fp32x4 -> hi fp16x4 (8B) + lo fp16x4 (8B)
__device__ __forceinline__ void split4(char* hi, char* lo, uint32_t off, float4 v) {
    __half2 h0 = __float22half2_rn(make_float2(v.x, v.y));
    __half2 h1 = __float22half2_rn(make_float2(v.z, v.w));
    float2 f0 = __half22float2(h0);
    float2 f1 = __half22float2(h1);
    __half2 l0 = __float22half2_rn(make_float2(v.x - f0.x, v.y - f0.y));
    __half2 l1 = __float22half2_rn(make_float2(v.z - f1.x, v.w - f1.y));
    *reinterpret_cast<uint2*>(hi + off) = make_uint2(h2u(h0), h2u(h1));
    *reinterpret_cast<uint2*>(lo + off) = make_uint2(h2u(l0), h2u(l1));
}

// ---------------------------------------------------------------------------
// emb2 = edge_emb @ W_msg^T
// ---------------------------------------------------------------------------
__global__ void emb2_kernel(const float* __restrict__ emb, const float* __restrict__ Wm) {
    int i = blockIdx.x, j = threadIdx.x;
    const float4* e4 = (const float4*)(emb + i * H);
    const float4* w4 = (const float4*)(Wm + j * H);
    float s = 0.f;
    #pragma unroll
    for (int k = 0; k < H / 4; k++) {
        float4 a = e4[k], b = w4[k];
        s += a.x * b.x + a.y * b.y + a.z * b.z + a.w * b.w;
    }
    g_emb2[i * H + j] = s;
}

// ---------------------------------------------------------------------------
// Tensor-core GEMM (persistent, fp16 2-pass split; lo pass fp16-acc):
//   D[:,0:128]   -> g_acc (fp32, + bself + bmsg)
//   D[:,128:256] -> g_y   (fp16)
// ---------------------------------------------------------------------------
__global__ __launch_bounds__(512, 1)
void gemm_tc_kernel(const float* __restrict__ x,
                    const float* __restrict__ Wself,
                    const float* __restrict__ Wmsg,
                    const float* __restrict__ bself,
                    const float* __restrict__ bmsg,
                    int N) {
    extern __shared__ char smem[];
    const uint32_t sb = smem_u32(smem);
    float* s_bias = (float*)(smem + SM_BIAS);

    const int tid  = threadIdx.x;
    const int wid  = tid >> 5, lane = tid & 31;
    const int wm   = (wid >> 3) * 64;
    const int wn   = (wid & 7) * 32;

    if (tid < H) s_bias[tid] = bself[tid] + bmsg[tid];

    {
        const int n  = tid >> 1;
        const int kh = (tid & 1) * 64;
        const float* wrow = (n < H) ? (Wself + (size_t)n * H) : (Wmsg + (size_t)(n - H) * H);
        const float4* w4 = (const float4*)(wrow + kh);
        char* dst = smem + SM_WHI + n * SXB + kh * 2;
        #pragma unroll 4
        for (int i = 0; i < 16; i++) {
            float4 v = w4[i];
            __half2 h0 = __float22half2_rn(make_float2(v.x, v.y));
            __half2 h1 = __float22half2_rn(make_float2(v.z, v.w));
            *reinterpret_cast<uint2*>(dst + i * 8) = make_uint2(h2u(h0), h2u(h1));
        }
    }
    __syncthreads();

    const uint32_t aHiB = sb + SM_XHI + (wm + (lane & 15)) * SXB + (lane >> 4) * 16;
    const uint32_t aLoB = sb + SM_XLO + (wm + (lane & 15)) * SXB + (lane >> 4) * 16;
    const uint32_t bB   = sb + SM_WHI + (wn + (lane & 15)) * SXB + (lane >> 4) * 16;

    const int ntiles = (N + 127) >> 7;
    const int fr = tid >> 2;
    const int fk = (tid & 3) * 32;

    for (int t = blockIdx.x; t < ntiles; t += gridDim.x) {
        const int row0 = t << 7;

        __syncthreads();

        {
            int gr = row0 + fr; if (gr > N - 1) gr = N - 1;
            const float4* xr = (const float4*)(x + (size_t)gr * H + fk);
            const uint32_t base = fr * SXB + fk * 2;
            #pragma unroll 8
            for (int i = 0; i < 8; i++)
                split4(smem + SM_XHI, smem + SM_XLO, base + i * 8, xr[i]);
        }
        __syncthreads();

        float acc[4][4][4];
        uint32_t accL[4][4][2];
        #pragma unroll
        for (int mt = 0; mt < 4; mt++)
            #pragma unroll
            for (int nt = 0; nt < 4; nt++) {
                #pragma unroll
                for (int j = 0; j < 4; j++) acc[mt][nt][j] = 0.f;
                accL[mt][nt][0] = accL[mt][nt][1] = 0u;
            }

        #pragma unroll
        for (int ks = 0; ks < 8; ks++) {
            const uint32_t ko = ks * 32;
            uint32_t bf[2][4];
            ldmx4(bf[0], bB + ko);
            ldmx4(bf[1], bB + 16 * SXB + ko);

            #pragma unroll
            for (int mt = 0; mt < 4; mt++) {
                uint32_t a[4];
                ldmx4(a, aHiB + mt * 16 * SXB + ko);
                mma_f32(acc[mt][0], a, bf[0][0], bf[0][2]);
                mma_f32(acc[mt][1], a, bf[0][1], bf[0][3]);
                mma_f32(acc[mt][2], a, bf[1][0], bf[1][2]);
                mma_f32(acc[mt][3], a, bf[1][1], bf[1][3]);
                ldmx4(a, aLoB + mt * 16 * SXB + ko);
                mma_f16(accL[mt][0], a, bf[0][0], bf[0][2]);
                mma_f16(accL[mt][1], a, bf[0][1], bf[0][3]);
                mma_f16(accL[mt][2], a, bf[1][0], bf[1][2]);
                mma_f16(accL[mt][3], a, bf[1][1], bf[1][3]);
            }
        }

        const int cbase = wn + (lane & 3) * 2;
        const bool self_half = (cbase < H);
        const int c = self_half ? cbase : cbase - H;
        float2 bias2 = make_float2(0.f, 0.f);

        #pragma unroll
        for (int nt = 0; nt < 4; nt++) {
            const int cc = c + nt * 8;
            if (self_half) bias2 = *(const float2*)&s_bias[cc];
            #pragma unroll
            for (int mt = 0; mt < 4; mt++) {
                const int r0 = row0 + wm + mt * 16 + (lane >> 2);
                const int r1 = r0 + 8;
                float2 lo0 = __half22float2(u2h(accL[mt][nt][0]));
                float2 lo1 = __half22float2(u2h(accL[mt][nt][1]));
                float2 v0 = make_float2(acc[mt][nt][0] + lo0.x, acc[mt][nt][1] + lo0.y);
                float2 v1 = make_float2(acc[mt][nt][2] + lo1.x, acc[mt][nt][3] + lo1.y);
                if (self_half) {
                    if (r0 < N)
                        *(float2*)&g_acc[(size_t)r0 * H + cc] =
                            make_float2(v0.x + bias2.x, v0.y + bias2.y);
                    if (r1 < N)
                        *(float2*)&g_acc[(size_t)r1 * H + cc] =
                            make_float2(v1.x + bias2.x, v1.y + bias2.y);
                } else {
                    if (r0 < N)
                        *(__half2*)&g_y[(size_t)r0 * H + cc] = __float22half2_rn(v0);
                    if (r1 < N)
                        *(__half2*)&g_y[(size_t)r1 * H + cc] = __float22half2_rn(v1);
                }
            }
        }
    }
}

// ---------------------------------------------------------------------------
// CSR build
// ---------------------------------------------------------------------------
__global__ __launch_bounds__(1024)
void zero_kernel(int N) {
    int i = blockIdx.x * 1024 + threadIdx.x;
    if (i < N) g_deg[i] = 0;
    if (i == 0) g_total = 0;
}

__global__ __launch_bounds__(512)
void hist_kernel(const int* __restrict__ ei, int E) {
    int i = blockIdx.x * 512 + threadIdx.x;
    int stride = gridDim.x * 512;
    for (int e = i; e < E; e += stride)
        atomicAdd(&g_deg[ei[E + e]], 1);
}

__global__ __launch_bounds__(256)
void assign_kernel(int N) {
    const int n    = blockIdx.x * 256 + threadIdx.x;
    const int lane = threadIdx.x & 31;
    int d = (n < N) ? g_deg[n] : 0;
    int s = d;
    #pragma unroll
    for (int o = 1; o < 32; o <<= 1) {
        int t = __shfl_up_sync(0xffffffffu, s, o);
        if (lane >= o) s += t;
    }
    int base = 0;
    if (lane == 31) base = atomicAdd(&g_total, s);
    base = __shfl_sync(0xffffffffu, base, 31);
    if (n < N) {
        int st = base + s - d;
        g_start[n]  = st;
        g_cursor[n] = st;
    }
}

__global__ __launch_bounds__(512)
void fill_kernel(const int* __restrict__ ei, const int* __restrict__ et, int E) {
    int i = blockIdx.x * 512 + threadIdx.x;
    int stride = gridDim.x * 512;
    for (int e = i; e < E; e += stride) {
        int src = ei[e];
        int dst = ei[E + e];
        int ty  = et[e];
        int slot = atomicAdd(&g_cursor[dst], 1);
        g_pk[slot] = src | (ty << 24);
    }
}

// ---------------------------------------------------------------------------
// Fused aggregate + ReLU + LayerNorm: one warp per node row (g_y is fp16)
// ---------------------------------------------------------------------------
__global__ __launch_bounds__(256)
void aggregate_ln_kernel(const float* __restrict__ gamma, const float* __restrict__ beta,
                         float* __restrict__ out, int N) {
    __shared__ float s_emb[NTYPES * H];
    for (int i = threadIdx.x; i < NTYPES * H; i += 256) s_emb[i] = g_emb2[i];
    __syncthreads();

    const int lane = threadIdx.x & 31;
    const int row  = blockIdx.x * 8 + (threadIdx.x >> 5);
    if (row >= N) return;
    const int off = lane * 4;

    float4 v = *(const float4*)&g_acc[(size_t)row * H + off];

    const int st = g_start[row];
    const int en = st + g_deg[row];
    for (int i = st; i < en; i++) {
        int p   = g_pk[i];
        int src = p & 0xFFFFFF;
        int ty  = p >> 24;
        uint2 mu = *(const uint2*)&g_y[(size_t)src * H + off];
        float2 m0 = __half22float2(u2h(mu.x));
        float2 m1 = __half22float2(u2h(mu.y));
        float4 em = *(const float4*)&s_emb[ty * H + off];
        v.x += m0.x + em.x; v.y += m0.y + em.y;
        v.z += m1.x + em.z; v.w += m1.y + em.w;
    }

    v.x = fmaxf(v.x, 0.f); v.y = fmaxf(v.y, 0.f);
    v.z = fmaxf(v.z, 0.f); v.w = fmaxf(v.w, 0.f);

    float s  = v.x + v.y + v.z + v.w;
    float sq = v.x * v.x + v.y * v.y + v.z * v.z + v.w * v.w;
    #pragma unroll
    for (int o = 16; o > 0; o >>= 1) {
        s  += __shfl_xor_sync(0xffffffffu, s,  o);
        sq += __shfl_xor_sync(0xffffffffu, sq, o);
    }
    float mean = s * (1.f / H);
    float var  = sq * (1.f / H) - mean * mean;
    float rstd = rsqrtf(var + 1e-5f);

    float4 g = *(const float4*)&gamma[off];
    float4 b = *(const float4*)&beta[off];
    float4 o;
    o.x = (v.x - mean) * rstd * g.x + b.x;
    o.y = (v.y - mean) * rstd * g.y + b.y;
    o.z = (v.z - mean) * rstd * g.z + b.z;
    o.w = (v.w - mean) * rstd * g.w + b.w;
    *(float4*)&out[(size_t)row * H + off] = o;
}

// ---------------------------------------------------------------------------
extern "C" void kernel_launch(void* const* d_in, const int* in_sizes, int n_in,
                              void* d_out, int out_size) {
    const float* x     = (const float*)d_in[0];
    const int*   ei    = (const int*)  d_in[1];
    const int*   et    = (const int*)  d_in[2];
    const float* emb   = (const float*)d_in[3];
    const float* Wself = (const float*)d_in[4];
    const float* bself = (const float*)d_in[5];
    const float* Wmsg  = (const float*)d_in[6];
    const float* bmsg  = (const float*)d_in[7];
    const float* gamma = (const float*)d_in[8];
    const float* beta  = (const float*)d_in[9];
    float* out = (float*)d_out;

    const int N = in_sizes[0] / H;
    const int E = in_sizes[1] / 2;

    cudaFuncSetAttribute(gemm_tc_kernel, cudaFuncAttributeMaxDynamicSharedMemorySize, SM_TOT);

    // Order chosen so gemm_tc_kernel sits at absolute launch index 3 (the slot
    // ncu samples), while respecting dependencies.
    zero_kernel<<<(N + 1023) / 1024, 1024>>>(N);
    emb2_kernel<<<NTYPES, H>>>(emb, Wmsg);
    hist_kernel<<<592, 512>>>(ei, E);
    gemm_tc_kernel<<<152, 512, SM_TOT>>>(x, Wself, Wmsg, bself, bmsg, N);
    assign_kernel<<<(N + 255) / 256, 256>>>(N);
    fill_kernel<<<592, 512>>>(ei, et, E);
    aggregate_ln_kernel<<<(N + 7) / 8, 256>>>(gamma, beta, out, N);
}